// round 12
// baseline (speedup 1.0000x reference)
#include <cuda_runtime.h>
#include <cuda_bf16.h>
#include <cuda_fp16.h>
#include <cstdint>

#define D_MODEL 768
#define NH      12
#define HEADD   64
#define BATCH   2
#define SEQ     2048
#define M_TOK   (BATCH*SEQ)   // 4096
#define N_QKV   (3*D_MODEL)   // 2304

// ============================================================
// helpers
// ============================================================
__device__ __forceinline__ uint32_t smem_u32(const void* p) {
    uint32_t a;
    asm("{ .reg .u64 t; cvta.to.shared.u64 t, %1; cvt.u32.u64 %0, t; }" : "=r"(a) : "l"(p));
    return a;
}

__device__ __forceinline__ void ldsm4(uint32_t* r, uint32_t addr) {
    asm volatile("ldmatrix.sync.aligned.m8n8.x4.shared.b16 {%0,%1,%2,%3}, [%4];"
        : "=r"(r[0]), "=r"(r[1]), "=r"(r[2]), "=r"(r[3]) : "r"(addr));
}
__device__ __forceinline__ void ldsm4t(uint32_t* r, uint32_t addr) {
    asm volatile("ldmatrix.sync.aligned.m8n8.x4.trans.shared.b16 {%0,%1,%2,%3}, [%4];"
        : "=r"(r[0]), "=r"(r[1]), "=r"(r[2]), "=r"(r[3]) : "r"(addr));
}

__device__ __forceinline__ void mma16816h(float* c, const uint32_t* a, const uint32_t* b) {
    asm volatile(
        "mma.sync.aligned.m16n8k16.row.col.f32.f16.f16.f32 "
        "{%0,%1,%2,%3}, {%4,%5,%6,%7}, {%8,%9}, {%0,%1,%2,%3};"
        : "+f"(c[0]), "+f"(c[1]), "+f"(c[2]), "+f"(c[3])
        : "r"(a[0]), "r"(a[1]), "r"(a[2]), "r"(a[3]), "r"(b[0]), "r"(b[1]));
}

__device__ __forceinline__ float ex2(float x) {
    float r;
    asm("ex2.approx.ftz.f32 %0, %1;" : "=f"(r) : "f"(x));
    return r;
}

#define SWZ(off) ((off) ^ (((off) >> 3) & 0x70))

__device__ __forceinline__ uint32_t pack2h(float a, float b) {
    __half2 h2 = __floats2half2_rn(a, b);
    return *(uint32_t*)&h2;
}

// ---- scratch (device globals; no allocations allowed) ----
__device__ __align__(16) __half g_xh[(size_t)M_TOK*D_MODEL];
__device__ __align__(16) __half g_w1h[(size_t)N_QKV*D_MODEL];
__device__ __align__(16) __half g_w2h[(size_t)D_MODEL*D_MODEL];
__device__ __align__(16) __half g_qh[(size_t)BATCH*NH*SEQ*HEADD];
__device__ __align__(16) __half g_kh[(size_t)BATCH*NH*SEQ*HEADD];
__device__ __align__(16) __half g_vh[(size_t)BATCH*NH*SEQ*HEADD];
__device__ __align__(16) __half g_oh[(size_t)M_TOK*D_MODEL];

// ============================================================
// fused converts: x, W1, W2 -> fp16
// ============================================================
static constexpr int XBLK  = (M_TOK*D_MODEL)/1024;            // 3072
static constexpr int W1BLK = (N_QKV*D_MODEL)/1024;            // 1728
static constexpr int W2BLK = (D_MODEL*D_MODEL)/1024;          // 576

__global__ __launch_bounds__(256)
void convert_all(const float* __restrict__ x, const float* __restrict__ W1,
                 const float* __restrict__ W2)
{
    int blk = blockIdx.x;
    const float* src;
    __half* dst;
    int i;
    if (blk < XBLK) {
        i = (blk * 256 + threadIdx.x) * 4;
        src = x; dst = g_xh;
    } else if (blk < XBLK + W1BLK) {
        i = ((blk - XBLK) * 256 + threadIdx.x) * 4;
        src = W1; dst = g_w1h;
    } else {
        i = ((blk - XBLK - W1BLK) * 256 + threadIdx.x) * 4;
        src = W2; dst = g_w2h;
    }
    float4 v = *(const float4*)(src + i);
    *(uint32_t*)(dst + i)     = pack2h(v.x, v.y);
    *(uint32_t*)(dst + i + 2) = pack2h(v.z, v.w);
}

// ============================================================
// fp16 1-pass GEMM via mma.sync
// 128x128 CTA, 8 warps, 3-buffer/2-in-flight cp.async, 1 barrier/chunk,
// 2 CTAs/SM.  MODE 0: emit fp16 q (scaled), k, v.  MODE 1: fp32 C + bias.
// ============================================================
static constexpr int GBK     = 64;
static constexpr int NCH     = D_MODEL / GBK;    // 12
static constexpr int TILE_B  = 128 * 128;        // 16 KB
static constexpr int STAGE_B = 2 * TILE_B;       // 32 KB (A + B tiles)
static constexpr int SMEM_GEMM = 3 * STAGE_B;    // 96 KB
#define QSCALE 0.18033688011112042f               // 0.125 * log2(e)

__device__ __forceinline__ void load_tile_async(uint32_t smem_tile, const __half* g,
                                                int row0, int k0, int tid)
{
    #pragma unroll
    for (int i = 0; i < 4; i++) {
        int u  = tid + i * 256;
        int r  = u >> 3;
        int cu = u & 7;
        uint32_t dst = smem_tile + SWZ((uint32_t)(r * 128 + cu * 16));
        const void* src = g + (size_t)(row0 + r) * D_MODEL + k0 + cu * 8;
        asm volatile("cp.async.cg.shared.global [%0], [%1], 16;" :: "r"(dst), "l"(src) : "memory");
    }
}

template<int MODE>
__global__ __launch_bounds__(256, 2)
void gemm_mma(const __half* __restrict__ Ah, const __half* __restrict__ Bh,
              const float* __restrict__ bias, float* __restrict__ C, int N)
{
    extern __shared__ __align__(1024) char smem[];
    const uint32_t sb = smem_u32(smem);
    const int tid  = threadIdx.x;
    const int wid  = tid >> 5;
    const int lane = tid & 31;
    const int wm   = wid & 1;
    const int wn   = wid >> 1;
    const int row0 = blockIdx.y * 128;
    const int col0 = blockIdx.x * 128;

    float acc[4][4][4] = {};

    const int aRow = wm * 64 + (lane & 15);
    const uint32_t xr = (uint32_t)((aRow & 7) << 4);
    const int aHalf = lane >> 4;
    const int bN = wn * 32 + (lane & 7) + ((lane >> 4) << 3);
    const uint32_t xn = (uint32_t)((lane & 7) << 4);
    const int bKb = ((lane >> 3) & 1) * 16;

    auto stage_addr = [&](int s) { return sb + (uint32_t)s * STAGE_B; };
    #pragma unroll
    for (int s0 = 0; s0 < 2; s0++) {
        uint32_t st = stage_addr(s0);
        load_tile_async(st,          Ah, row0, s0*GBK, tid);
        load_tile_async(st + TILE_B, Bh, col0, s0*GBK, tid);
        asm volatile("cp.async.commit_group;" ::: "memory");
    }

    for (int c = 0; c < NCH; c++) {
        const int s = c % 3;
        if (c < NCH - 1) asm volatile("cp.async.wait_group 1;" ::: "memory");
        else             asm volatile("cp.async.wait_group 0;" ::: "memory");
        __syncthreads();

        // prefetch chunk c+2 into stage (c+2)%3 (quiescent since iter c-1 done)
        if (c + 2 < NCH) {
            uint32_t st2 = stage_addr((c + 2) % 3);
            int k0 = (c + 2) * GBK;
            load_tile_async(st2,          Ah, row0, k0, tid);
            load_tile_async(st2 + TILE_B, Bh, col0, k0, tid);
            asm volatile("cp.async.commit_group;" ::: "memory");
        }

        const uint32_t stAh = stage_addr(s);
        const uint32_t stBh = stAh + TILE_B;

        #pragma unroll
        for (int ks = 0; ks < 4; ks++) {
            const uint32_t aKx = (uint32_t)((ks*32 + aHalf*16)) ^ xr;
            const uint32_t bKx = (uint32_t)((ks*32 + bKb)) ^ xn;

            uint32_t Afh[4][4], Bfh[2][4];
            #pragma unroll
            for (int mi = 0; mi < 4; mi++) {
                uint32_t off = (uint32_t)((aRow + mi*16) * 128) + aKx;
                ldsm4(Afh[mi], stAh + off);
            }
            #pragma unroll
            for (int j2 = 0; j2 < 2; j2++) {
                uint32_t off = (uint32_t)((bN + j2*16) * 128) + bKx;
                ldsm4(Bfh[j2], stBh + off);
            }
            #pragma unroll
            for (int mi = 0; mi < 4; mi++) {
                #pragma unroll
                for (int nj = 0; nj < 4; nj++) {
                    mma16816h(acc[mi][nj], Afh[mi], &Bfh[nj >> 1][(nj & 1) * 2]);
                }
            }
        }
    }

    #pragma unroll
    for (int mi = 0; mi < 4; mi++) {
        #pragma unroll
        for (int h2 = 0; h2 < 2; h2++) {
            const int m  = row0 + wm*64 + mi*16 + h2*8 + (lane >> 2);
            const int bb = m >> 11;
            const int t  = m & (SEQ - 1);
            #pragma unroll
            for (int nj = 0; nj < 4; nj++) {
                const int f = col0 + wn*32 + nj*8 + (lane & 3)*2;
                float vx = acc[mi][nj][h2*2+0] + bias[f];
                float vy = acc[mi][nj][h2*2+1] + bias[f+1];
                if (MODE == 0) {
                    int which = (f >= 1536) ? 2 : (f >= 768 ? 1 : 0);
                    int cc = f - which * 768;
                    int h = cc >> 6, d = cc & 63;
                    size_t idx = (((size_t)(bb*NH + h))*SEQ + t)*HEADD + d;
                    if (which == 0) {
                        *(uint32_t*)&g_qh[idx] = pack2h(vx * QSCALE, vy * QSCALE);
                    } else {
                        __half* dst = (which == 1) ? g_kh : g_vh;
                        *(uint32_t*)&dst[idx] = pack2h(vx, vy);
                    }
                } else {
                    float2 v; v.x = vx; v.y = vy;
                    *(float2*)&C[(size_t)m * N + f] = v;
                }
            }
        }
    }
}

// ============================================================
// Tensor-core flash attention (causal), exp2 softmax, all 1-pass fp16.
// Grid (16, 24): 128 queries per CTA per head, 8 warps, 2 CTAs/SM.
// kv chunks of 128 rows, 3-buffer/2-in-flight cp.async, 1 barrier/chunk.
// ============================================================
static constexpr int AQ_H  = 0;                   // Q: 16 KB
static constexpr int AST0  = 16384;               // 3 stages: Kh(16KB)+Vh(16KB)
static constexpr int ASTG  = 32768;
static constexpr int SMEM_ATTN = 16384 + 3*ASTG;  // 112 KB

__device__ __forceinline__ void load_kv_async(uint32_t st, const __half* Kh,
                                              const __half* Vh, int kc, int tid)
{
    #pragma unroll
    for (int i = 0; i < 4; i++) {
        int u  = tid + i * 256;      // 0..1023
        int r  = u >> 3;             // 0..127
        int cu = u & 7;
        uint32_t dsw = SWZ((uint32_t)(r * 128 + cu * 16));
        size_t src = (size_t)(kc + r) * HEADD + cu * 8;
        asm volatile("cp.async.cg.shared.global [%0], [%1], 16;" :: "r"(st + dsw),         "l"((const void*)(Kh + src)) : "memory");
        asm volatile("cp.async.cg.shared.global [%0], [%1], 16;" :: "r"(st + 16384 + dsw), "l"((const void*)(Vh + src)) : "memory");
    }
}

__global__ __launch_bounds__(256, 2)
void attn_mma()
{
    extern __shared__ __align__(1024) char smem[];
    const uint32_t sb = smem_u32(smem);
    const int tid  = threadIdx.x;
    const int wid  = tid >> 5;
    const int lane = tid & 31;
    const int bh   = blockIdx.y;
    const int qt   = gridDim.x - 1 - blockIdx.x;   // heavy CTAs first
    const int q0   = qt * 128;
    const int m0   = wid * 16;
    const int nch  = qt + 1;

    const size_t hoff = (size_t)bh * SEQ * HEADD;
    const __half* Qh = g_qh + hoff;
    const __half* Kh = g_kh + hoff;
    const __half* Vh = g_vh + hoff;

    // prologue: Q + chunk0 in group 0, chunk1 in group 1
    #pragma unroll
    for (int i = 0; i < 4; i++) {
        int u  = tid + i * 256;
        int r  = u >> 3;
        int cu = u & 7;
        uint32_t dsw = SWZ((uint32_t)(r * 128 + cu * 16));
        size_t src = (size_t)(q0 + r) * HEADD + cu * 8;
        asm volatile("cp.async.cg.shared.global [%0], [%1], 16;" :: "r"(sb + AQ_H + dsw), "l"((const void*)(Qh + src)) : "memory");
    }
    load_kv_async(sb + AST0, Kh, Vh, 0, tid);
    asm volatile("cp.async.commit_group;" ::: "memory");
    if (nch > 1) {
        load_kv_async(sb + AST0 + ASTG, Kh, Vh, 128, tid);
    }
    asm volatile("cp.async.commit_group;" ::: "memory");

    uint32_t QfH[4][4];
    float o[8][4] = {};
    float m_[2] = {-1e30f, -1e30f};
    float l_[2] = {0.f, 0.f};

    const uint32_t aoff0 = (uint32_t)((m0 + (lane & 15)) * 128);
    const int aHalf = (lane >> 4) * 16;
    const int krow = (lane & 7) + ((lane >> 4) << 3);
    const int kcb  = ((lane >> 3) & 1) * 16;
    const int vg   = lane >> 3;
    const int vr   = lane & 7;

    for (int c = 0; c < nch; c++) {
        const int s = c % 3;
        if (c < nch - 1) asm volatile("cp.async.wait_group 1;" ::: "memory");
        else             asm volatile("cp.async.wait_group 0;" ::: "memory");
        __syncthreads();

        // prefetch chunk c+2 into stage (c+2)%3 (quiescent: iter c-1 done by sync)
        if (c + 2 < nch) {
            load_kv_async(sb + AST0 + (uint32_t)((c + 2) % 3) * ASTG, Kh, Vh, (c + 2) * 128, tid);
            asm volatile("cp.async.commit_group;" ::: "memory");
        } else {
            asm volatile("cp.async.commit_group;" ::: "memory");   // keep group count in step
        }

        if (c == 0) {
            #pragma unroll
            for (int kc = 0; kc < 4; kc++) {
                uint32_t off = SWZ(aoff0 + (uint32_t)(kc*32 + aHalf));
                ldsm4(QfH[kc], sb + AQ_H + off);
            }
        }

        const uint32_t stK = sb + AST0 + (uint32_t)s * ASTG;
        const uint32_t stV = stK + 16384;
        const bool diag = (c == nch - 1);   // only final chunk intersects diagonal

        // ---- S = Q K^T (1-pass) ----
        float sc[16][4];
        #pragma unroll
        for (int nj = 0; nj < 16; nj++) { sc[nj][0]=0.f; sc[nj][1]=0.f; sc[nj][2]=0.f; sc[nj][3]=0.f; }
        #pragma unroll
        for (int np = 0; np < 8; np++) {
            if (diag && np*16 > m0 + 15) {   // fully masked subtile: skip mma
                sc[2*np][0]=sc[2*np][1]=sc[2*np][2]=sc[2*np][3]=-1e30f;
                sc[2*np+1][0]=sc[2*np+1][1]=sc[2*np+1][2]=sc[2*np+1][3]=-1e30f;
                continue;
            }
            #pragma unroll
            for (int kc = 0; kc < 4; kc++) {
                uint32_t off = SWZ((uint32_t)((np*16 + krow) * 128 + kc*32 + kcb));
                uint32_t Bf[4];
                ldsm4(Bf, stK + off);
                mma16816h(sc[2*np],   QfH[kc], &Bf[0]);
                mma16816h(sc[2*np+1], QfH[kc], &Bf[2]);
            }
        }

        // ---- elementwise causal mask (diagonal chunk only) ----
        if (diag) {
            const int qr0 = m0 + (lane >> 2);       // relative to chunk base (= q0)
            const int cb  = (lane & 3)*2;
            #pragma unroll
            for (int nj = 0; nj < 16; nj++) {
                int col = cb + nj*8;
                if (col     > qr0)     sc[nj][0] = -1e30f;
                if (col + 1 > qr0)     sc[nj][1] = -1e30f;
                if (col     > qr0 + 8) sc[nj][2] = -1e30f;
                if (col + 1 > qr0 + 8) sc[nj][3] = -1e30f;
            }
        }

        // ---- online softmax (exp2; scores pre-scaled by log2e) ----
        #pragma unroll
        for (int rr = 0; rr < 2; rr++) {
            float mx = -1e30f;
            #pragma unroll
            for (int nj = 0; nj < 16; nj++)
                mx = fmaxf(mx, fmaxf(sc[nj][2*rr], sc[nj][2*rr+1]));
            mx = fmaxf(mx, __shfl_xor_sync(0xffffffffu, mx, 1));
            mx = fmaxf(mx, __shfl_xor_sync(0xffffffffu, mx, 2));
            float mn   = fmaxf(m_[rr], mx);
            float corr = ex2(m_[rr] - mn);
            float rs = 0.f;
            #pragma unroll
            for (int nj = 0; nj < 16; nj++) {
                float p0 = ex2(sc[nj][2*rr]   - mn);
                float p1 = ex2(sc[nj][2*rr+1] - mn);
                sc[nj][2*rr]   = p0;
                sc[nj][2*rr+1] = p1;
                rs += p0 + p1;
            }
            rs += __shfl_xor_sync(0xffffffffu, rs, 1);
            rs += __shfl_xor_sync(0xffffffffu, rs, 2);
            l_[rr] = l_[rr] * corr + rs;
            m_[rr] = mn;
            #pragma unroll
            for (int nj = 0; nj < 8; nj++) {
                o[nj][2*rr]   *= corr;
                o[nj][2*rr+1] *= corr;
            }
        }

        // ---- O += P V (1-pass fp16 P) ----
        #pragma unroll
        for (int jc = 0; jc < 8; jc++) {
            if (diag && jc*16 > m0 + 15) continue;   // P block exactly zero
            uint32_t AH[4];
            AH[0] = pack2h(sc[2*jc][0],   sc[2*jc][1]);
            AH[1] = pack2h(sc[2*jc][2],   sc[2*jc][3]);
            AH[2] = pack2h(sc[2*jc+1][0], sc[2*jc+1][1]);
            AH[3] = pack2h(sc[2*jc+1][2], sc[2*jc+1][3]);
            #pragma unroll
            for (int dp = 0; dp < 4; dp++) {
                uint32_t off = SWZ((uint32_t)((jc*16 + (vg & 1)*8 + vr) * 128 + (dp*16 + (vg >> 1)*8) * 2));
                uint32_t Vf[4];
                ldsm4t(Vf, stV + off);
                mma16816h(o[2*dp],   AH, &Vf[0]);
                mma16816h(o[2*dp+1], AH, &Vf[2]);
            }
        }
    }

    // ---- epilogue: O/l -> fp16 in (token, 768) layout ----
    const int b = bh / NH;
    const int h = bh - b * NH;
    const float inv0 = 1.f / l_[0];
    const float inv1 = 1.f / l_[1];
    const int q = q0 + m0 + (lane >> 2);
    const size_t tok0 = (size_t)(b * SEQ + q) * D_MODEL;
    const size_t tok1 = tok0 + 8 * D_MODEL;
    #pragma unroll
    for (int nj = 0; nj < 8; nj++) {
        const int dc = h * HEADD + nj*8 + (lane & 3)*2;
        *(uint32_t*)&g_oh[tok0 + dc] = pack2h(o[nj][0] * inv0, o[nj][1] * inv0);
        *(uint32_t*)&g_oh[tok1 + dc] = pack2h(o[nj][2] * inv1, o[nj][3] * inv1);
    }
}

// ============================================================
extern "C" void kernel_launch(void* const* d_in, const int* in_sizes, int n_in,
                              void* d_out, int out_size)
{
    const float* x  = (const float*)d_in[0];   // (B,T,768)
    const float* W1 = (const float*)d_in[1];   // (2304,768)
    const float* b1 = (const float*)d_in[2];
    const float* W2 = (const float*)d_in[3];   // (768,768)
    const float* b2 = (const float*)d_in[4];
    float* out = (float*)d_out;

    __half *p_xh, *p_w1h, *p_w2h, *p_oh;
    cudaGetSymbolAddress((void**)&p_xh,  g_xh);
    cudaGetSymbolAddress((void**)&p_w1h, g_w1h);
    cudaGetSymbolAddress((void**)&p_w2h, g_w2h);
    cudaGetSymbolAddress((void**)&p_oh,  g_oh);

    cudaFuncSetAttribute(gemm_mma<0>, cudaFuncAttributeMaxDynamicSharedMemorySize, SMEM_GEMM);
    cudaFuncSetAttribute(gemm_mma<1>, cudaFuncAttributeMaxDynamicSharedMemorySize, SMEM_GEMM);
    cudaFuncSetAttribute(attn_mma,    cudaFuncAttributeMaxDynamicSharedMemorySize, SMEM_ATTN);

    // fused converts (all plain fp16 packs)
    convert_all<<<XBLK + W1BLK + W2BLK, 256>>>(x, W1, W2);

    // 1) QKV projection (fp16 1-pass) -> q (scaled 1/8*log2e), k, v
    gemm_mma<0><<<dim3(N_QKV/128, M_TOK/128), 256, SMEM_GEMM>>>(
        p_xh, p_w1h, b1, nullptr, N_QKV);

    // 2) tensor-core causal flash attention (all fp16 1-pass) -> fp16 O
    attn_mma<<<dim3(SEQ/128, BATCH*NH), 256, SMEM_ATTN>>>();

    // 3) output projection (fp16 1-pass)
    gemm_mma<1><<<dim3(D_MODEL/128, M_TOK/128), 256, SMEM_GEMM>>>(
        p_oh, p_w2h, b2, out, D_MODEL);
}

// round 13
// speedup vs baseline: 1.3470x; 1.3470x over previous
#include <cuda_runtime.h>
#include <cuda_bf16.h>
#include <cuda_fp16.h>
#include <cstdint>

#define D_MODEL 768
#define NH      12
#define HEADD   64
#define BATCH   2
#define SEQ     2048
#define M_TOK   (BATCH*SEQ)   // 4096
#define N_QKV   (3*D_MODEL)   // 2304

// ============================================================
// helpers
// ============================================================
__device__ __forceinline__ uint32_t smem_u32(const void* p) {
    uint32_t a;
    asm("{ .reg .u64 t; cvta.to.shared.u64 t, %1; cvt.u32.u64 %0, t; }" : "=r"(a) : "l"(p));
    return a;
}

__device__ __forceinline__ void ldsm4(uint32_t* r, uint32_t addr) {
    asm volatile("ldmatrix.sync.aligned.m8n8.x4.shared.b16 {%0,%1,%2,%3}, [%4];"
        : "=r"(r[0]), "=r"(r[1]), "=r"(r[2]), "=r"(r[3]) : "r"(addr));
}
__device__ __forceinline__ void ldsm4t(uint32_t* r, uint32_t addr) {
    asm volatile("ldmatrix.sync.aligned.m8n8.x4.trans.shared.b16 {%0,%1,%2,%3}, [%4];"
        : "=r"(r[0]), "=r"(r[1]), "=r"(r[2]), "=r"(r[3]) : "r"(addr));
}

__device__ __forceinline__ void mma16816h(float* c, const uint32_t* a, const uint32_t* b) {
    asm volatile(
        "mma.sync.aligned.m16n8k16.row.col.f32.f16.f16.f32 "
        "{%0,%1,%2,%3}, {%4,%5,%6,%7}, {%8,%9}, {%0,%1,%2,%3};"
        : "+f"(c[0]), "+f"(c[1]), "+f"(c[2]), "+f"(c[3])
        : "r"(a[0]), "r"(a[1]), "r"(a[2]), "r"(a[3]), "r"(b[0]), "r"(b[1]));
}

__device__ __forceinline__ float ex2(float x) {
    float r;
    asm("ex2.approx.ftz.f32 %0, %1;" : "=f"(r) : "f"(x));
    return r;
}

// exp2 of two (fp32 - mn) values, result packed fp16x2 (PV A-fragment word)
__device__ __forceinline__ uint32_t exp2pk(float a, float b, float mn) {
    __half2 h = __floats2half2_rn(a - mn, b - mn);
    uint32_t u = *(uint32_t*)&h;
    uint32_t r;
    asm("ex2.approx.f16x2 %0, %1;" : "=r"(r) : "r"(u));
    return r;
}

#define SWZ(off) ((off) ^ (((off) >> 3) & 0x70))

__device__ __forceinline__ uint32_t pack2h(float a, float b) {
    __half2 h2 = __floats2half2_rn(a, b);
    return *(uint32_t*)&h2;
}

// ---- scratch (device globals; no allocations allowed) ----
__device__ __align__(16) __half g_xh[(size_t)M_TOK*D_MODEL];
__device__ __align__(16) __half g_w1h[(size_t)N_QKV*D_MODEL];
__device__ __align__(16) __half g_w2h[(size_t)D_MODEL*D_MODEL];
__device__ __align__(16) __half g_qh[(size_t)BATCH*NH*SEQ*HEADD];
__device__ __align__(16) __half g_kh[(size_t)BATCH*NH*SEQ*HEADD];
__device__ __align__(16) __half g_vh[(size_t)BATCH*NH*SEQ*HEADD];
__device__ __align__(16) __half g_oh[(size_t)M_TOK*D_MODEL];

// ============================================================
// fused converts: x, W1, W2 -> fp16
// ============================================================
static constexpr int XBLK  = (M_TOK*D_MODEL)/1024;            // 3072
static constexpr int W1BLK = (N_QKV*D_MODEL)/1024;            // 1728
static constexpr int W2BLK = (D_MODEL*D_MODEL)/1024;          // 576

__global__ __launch_bounds__(256)
void convert_all(const float* __restrict__ x, const float* __restrict__ W1,
                 const float* __restrict__ W2)
{
    int blk = blockIdx.x;
    const float* src;
    __half* dst;
    int i;
    if (blk < XBLK) {
        i = (blk * 256 + threadIdx.x) * 4;
        src = x; dst = g_xh;
    } else if (blk < XBLK + W1BLK) {
        i = ((blk - XBLK) * 256 + threadIdx.x) * 4;
        src = W1; dst = g_w1h;
    } else {
        i = ((blk - XBLK - W1BLK) * 256 + threadIdx.x) * 4;
        src = W2; dst = g_w2h;
    }
    float4 v = *(const float4*)(src + i);
    *(uint32_t*)(dst + i)     = pack2h(v.x, v.y);
    *(uint32_t*)(dst + i + 2) = pack2h(v.z, v.w);
}

// ============================================================
// fp16 1-pass GEMM via mma.sync (128x128 CTA, 8 warps, 2-stage, 2 CTA/SM)
// MODE 0: emit fp16 q (scaled 1/8*log2e), k, v.  MODE 1: fp32 C + bias.
// ============================================================
static constexpr int GBK     = 64;
static constexpr int NCH     = D_MODEL / GBK;    // 12
static constexpr int TILE_B  = 128 * 128;        // 16 KB
static constexpr int STAGE_B = 2 * TILE_B;       // 32 KB
static constexpr int SMEM_GEMM = 2 * STAGE_B;    // 64 KB
#define QSCALE 0.18033688011112042f               // 0.125 * log2(e)

__device__ __forceinline__ void load_tile_async(uint32_t smem_tile, const __half* g,
                                                int row0, int k0, int tid)
{
    #pragma unroll
    for (int i = 0; i < 4; i++) {
        int u  = tid + i * 256;
        int r  = u >> 3;
        int cu = u & 7;
        uint32_t dst = smem_tile + SWZ((uint32_t)(r * 128 + cu * 16));
        const void* src = g + (size_t)(row0 + r) * D_MODEL + k0 + cu * 8;
        asm volatile("cp.async.cg.shared.global [%0], [%1], 16;" :: "r"(dst), "l"(src) : "memory");
    }
}

template<int MODE>
__global__ __launch_bounds__(256, 2)
void gemm_mma(const __half* __restrict__ Ah, const __half* __restrict__ Bh,
              const float* __restrict__ bias, float* __restrict__ C, int N)
{
    extern __shared__ __align__(1024) char smem[];
    const uint32_t sb = smem_u32(smem);
    const int tid  = threadIdx.x;
    const int wid  = tid >> 5;
    const int lane = tid & 31;
    const int wm   = wid & 1;
    const int wn   = wid >> 1;
    const int row0 = blockIdx.y * 128;
    const int col0 = blockIdx.x * 128;

    float acc[4][4][4] = {};

    const int aRow = wm * 64 + (lane & 15);
    const uint32_t xr = (uint32_t)((aRow & 7) << 4);
    const int aHalf = lane >> 4;
    const int bN = wn * 32 + (lane & 7) + ((lane >> 4) << 3);
    const uint32_t xn = (uint32_t)((lane & 7) << 4);
    const int bKb = ((lane >> 3) & 1) * 16;

    auto stage_addr = [&](int s) { return sb + (uint32_t)s * STAGE_B; };
    #pragma unroll
    for (int s0 = 0; s0 < 2; s0++) {
        uint32_t st = stage_addr(s0);
        load_tile_async(st,          Ah, row0, s0*GBK, tid);
        load_tile_async(st + TILE_B, Bh, col0, s0*GBK, tid);
        asm volatile("cp.async.commit_group;" ::: "memory");
    }

    for (int c = 0; c < NCH; c++) {
        const int s = c & 1;
        if (c < NCH - 1) asm volatile("cp.async.wait_group 1;" ::: "memory");
        else             asm volatile("cp.async.wait_group 0;" ::: "memory");
        __syncthreads();

        const uint32_t stAh = stage_addr(s);
        const uint32_t stBh = stAh + TILE_B;

        #pragma unroll
        for (int ks = 0; ks < 4; ks++) {
            const uint32_t aKx = (uint32_t)((ks*32 + aHalf*16)) ^ xr;
            const uint32_t bKx = (uint32_t)((ks*32 + bKb)) ^ xn;

            uint32_t Afh[4][4], Bfh[2][4];
            #pragma unroll
            for (int mi = 0; mi < 4; mi++) {
                uint32_t off = (uint32_t)((aRow + mi*16) * 128) + aKx;
                ldsm4(Afh[mi], stAh + off);
            }
            #pragma unroll
            for (int j2 = 0; j2 < 2; j2++) {
                uint32_t off = (uint32_t)((bN + j2*16) * 128) + bKx;
                ldsm4(Bfh[j2], stBh + off);
            }
            #pragma unroll
            for (int mi = 0; mi < 4; mi++) {
                #pragma unroll
                for (int nj = 0; nj < 4; nj++) {
                    mma16816h(acc[mi][nj], Afh[mi], &Bfh[nj >> 1][(nj & 1) * 2]);
                }
            }
        }
        __syncthreads();

        if (c + 2 < NCH) {
            uint32_t st2 = stage_addr(s);
            int k0 = (c + 2) * GBK;
            load_tile_async(st2,          Ah, row0, k0, tid);
            load_tile_async(st2 + TILE_B, Bh, col0, k0, tid);
            asm volatile("cp.async.commit_group;" ::: "memory");
        }
    }

    #pragma unroll
    for (int mi = 0; mi < 4; mi++) {
        #pragma unroll
        for (int h2 = 0; h2 < 2; h2++) {
            const int m  = row0 + wm*64 + mi*16 + h2*8 + (lane >> 2);
            const int bb = m >> 11;
            const int t  = m & (SEQ - 1);
            #pragma unroll
            for (int nj = 0; nj < 4; nj++) {
                const int f = col0 + wn*32 + nj*8 + (lane & 3)*2;
                float vx = acc[mi][nj][h2*2+0] + bias[f];
                float vy = acc[mi][nj][h2*2+1] + bias[f+1];
                if (MODE == 0) {
                    int which = (f >= 1536) ? 2 : (f >= 768 ? 1 : 0);
                    int cc = f - which * 768;
                    int h = cc >> 6, d = cc & 63;
                    size_t idx = (((size_t)(bb*NH + h))*SEQ + t)*HEADD + d;
                    if (which == 0) {
                        *(uint32_t*)&g_qh[idx] = pack2h(vx * QSCALE, vy * QSCALE);
                    } else {
                        __half* dst = (which == 1) ? g_kh : g_vh;
                        *(uint32_t*)&dst[idx] = pack2h(vx, vy);
                    }
                } else {
                    float2 v; v.x = vx; v.y = vy;
                    *(float2*)&C[(size_t)m * N + f] = v;
                }
            }
        }
    }
}

// ============================================================
// Tensor-core flash attention (causal), all 1-pass fp16.
// exp via ex2.approx.f16x2 straight into PV fragments;
// l via ones-mma on the tensor pipe (no scalar row-sum).
// Grid (16, 24): 128 queries per CTA per head, 8 warps, 1 CTA/SM.
// kv chunks of 128 rows, 2-stage cp.async, diag subtile skipping.
// ============================================================
static constexpr int AQ_H  = 0;                  // Q: 16 KB
static constexpr int AST0  = 16384;              // stages: Kh(16KB), Vh(16KB)
static constexpr int ASTG  = 32768;
static constexpr int SMEM_ATTN = 16384 + 2*ASTG; // 80 KB

__device__ __forceinline__ void load_kv_async(uint32_t st, const __half* Kh,
                                              const __half* Vh, int kc, int tid)
{
    #pragma unroll
    for (int i = 0; i < 4; i++) {
        int u  = tid + i * 256;      // 0..1023
        int r  = u >> 3;             // 0..127
        int cu = u & 7;
        uint32_t dsw = SWZ((uint32_t)(r * 128 + cu * 16));
        size_t src = (size_t)(kc + r) * HEADD + cu * 8;
        asm volatile("cp.async.cg.shared.global [%0], [%1], 16;" :: "r"(st + dsw),         "l"((const void*)(Kh + src)) : "memory");
        asm volatile("cp.async.cg.shared.global [%0], [%1], 16;" :: "r"(st + 16384 + dsw), "l"((const void*)(Vh + src)) : "memory");
    }
}

__global__ __launch_bounds__(256, 1)
void attn_mma()
{
    extern __shared__ __align__(1024) char smem[];
    const uint32_t sb = smem_u32(smem);
    const int tid  = threadIdx.x;
    const int wid  = tid >> 5;
    const int lane = tid & 31;
    const int bh   = blockIdx.y;
    const int qt   = gridDim.x - 1 - blockIdx.x;   // heavy CTAs first
    const int q0   = qt * 128;
    const int m0   = wid * 16;
    const int nch  = qt + 1;

    const size_t hoff = (size_t)bh * SEQ * HEADD;
    const __half* Qh = g_qh + hoff;
    const __half* Kh = g_kh + hoff;
    const __half* Vh = g_vh + hoff;

    #pragma unroll
    for (int i = 0; i < 4; i++) {
        int u  = tid + i * 256;
        int r  = u >> 3;
        int cu = u & 7;
        uint32_t dsw = SWZ((uint32_t)(r * 128 + cu * 16));
        size_t src = (size_t)(q0 + r) * HEADD + cu * 8;
        asm volatile("cp.async.cg.shared.global [%0], [%1], 16;" :: "r"(sb + AQ_H + dsw), "l"((const void*)(Qh + src)) : "memory");
    }
    load_kv_async(sb + AST0, Kh, Vh, 0, tid);
    asm volatile("cp.async.commit_group;" ::: "memory");
    load_kv_async(sb + AST0 + ASTG, Kh, Vh, 128, tid);
    asm volatile("cp.async.commit_group;" ::: "memory");

    uint32_t QfH[4][4];
    float o[8][4] = {};
    float lacc[4] = {};                       // row-sum accumulator (ones-mma)
    float m_[2] = {-1e30f, -1e30f};

    const uint32_t aoff0 = (uint32_t)((m0 + (lane & 15)) * 128);
    const int aHalf = (lane >> 4) * 16;
    const int krow = (lane & 7) + ((lane >> 4) << 3);
    const int kcb  = ((lane >> 3) & 1) * 16;
    const int vg   = lane >> 3;
    const int vr   = lane & 7;
    const uint32_t onesB[2] = {0x3C003C00u, 0x3C003C00u};   // fp16 1.0 x4

    for (int c = 0; c < nch; c++) {
        const int s = c & 1;
        if (c < nch - 1) asm volatile("cp.async.wait_group 1;" ::: "memory");
        else             asm volatile("cp.async.wait_group 0;" ::: "memory");
        __syncthreads();

        if (c == 0) {
            #pragma unroll
            for (int kc = 0; kc < 4; kc++) {
                uint32_t off = SWZ(aoff0 + (uint32_t)(kc*32 + aHalf));
                ldsm4(QfH[kc], sb + AQ_H + off);
            }
        }

        const uint32_t stK = sb + AST0 + (uint32_t)s * ASTG;
        const uint32_t stV = stK + 16384;
        const bool diag = (c == nch - 1);   // only final chunk intersects diagonal

        // ---- S = Q K^T (1-pass) ----
        float sc[16][4];
        #pragma unroll
        for (int nj = 0; nj < 16; nj++) { sc[nj][0]=0.f; sc[nj][1]=0.f; sc[nj][2]=0.f; sc[nj][3]=0.f; }
        #pragma unroll
        for (int np = 0; np < 8; np++) {
            if (diag && np*16 > m0 + 15) {   // fully masked subtile: skip mma
                sc[2*np][0]=sc[2*np][1]=sc[2*np][2]=sc[2*np][3]=-1e30f;
                sc[2*np+1][0]=sc[2*np+1][1]=sc[2*np+1][2]=sc[2*np+1][3]=-1e30f;
                continue;
            }
            #pragma unroll
            for (int kc = 0; kc < 4; kc++) {
                uint32_t off = SWZ((uint32_t)((np*16 + krow) * 128 + kc*32 + kcb));
                uint32_t Bf[4];
                ldsm4(Bf, stK + off);
                mma16816h(sc[2*np],   QfH[kc], &Bf[0]);
                mma16816h(sc[2*np+1], QfH[kc], &Bf[2]);
            }
        }

        // ---- elementwise causal mask (diagonal chunk only) ----
        if (diag) {
            const int qr0 = m0 + (lane >> 2);       // relative to chunk base (= q0)
            const int cb  = (lane & 3)*2;
            #pragma unroll
            for (int nj = 0; nj < 16; nj++) {
                int col = cb + nj*8;
                if (col     > qr0)     sc[nj][0] = -1e30f;
                if (col + 1 > qr0)     sc[nj][1] = -1e30f;
                if (col     > qr0 + 8) sc[nj][2] = -1e30f;
                if (col + 1 > qr0 + 8) sc[nj][3] = -1e30f;
            }
        }

        // ---- online softmax: running max + rescale only ----
        float mn01[2];
        #pragma unroll
        for (int rr = 0; rr < 2; rr++) {
            float mx = -1e30f;
            #pragma unroll
            for (int nj = 0; nj < 16; nj++)
                mx = fmaxf(mx, fmaxf(sc[nj][2*rr], sc[nj][2*rr+1]));
            mx = fmaxf(mx, __shfl_xor_sync(0xffffffffu, mx, 1));
            mx = fmaxf(mx, __shfl_xor_sync(0xffffffffu, mx, 2));
            float mn   = fmaxf(m_[rr], mx);
            float corr = ex2(m_[rr] - mn);
            m_[rr]  = mn;
            mn01[rr] = mn;
            #pragma unroll
            for (int nj = 0; nj < 8; nj++) {
                o[nj][2*rr]   *= corr;
                o[nj][2*rr+1] *= corr;
            }
            lacc[2*rr]   *= corr;
            lacc[2*rr+1] *= corr;
        }

        // ---- P = exp2(S - mn) (f16x2 MUFU, direct A-fragment);
        //      l += P·1 (ones-mma);  O += P V ----
        #pragma unroll
        for (int jc = 0; jc < 8; jc++) {
            if (diag && jc*16 > m0 + 15) continue;   // P block exactly zero
            uint32_t P[4];
            P[0] = exp2pk(sc[2*jc][0],   sc[2*jc][1],   mn01[0]);
            P[1] = exp2pk(sc[2*jc][2],   sc[2*jc][3],   mn01[1]);
            P[2] = exp2pk(sc[2*jc+1][0], sc[2*jc+1][1], mn01[0]);
            P[3] = exp2pk(sc[2*jc+1][2], sc[2*jc+1][3], mn01[1]);
            mma16816h(lacc, P, onesB);
            #pragma unroll
            for (int dp = 0; dp < 4; dp++) {
                uint32_t off = SWZ((uint32_t)((jc*16 + (vg & 1)*8 + vr) * 128 + (dp*16 + (vg >> 1)*8) * 2));
                uint32_t Vf[4];
                ldsm4t(Vf, stV + off);
                mma16816h(o[2*dp],   P, &Vf[0]);
                mma16816h(o[2*dp+1], P, &Vf[2]);
            }
        }

        __syncthreads();
        if (c + 2 < nch) {
            load_kv_async(sb + AST0 + (uint32_t)s * ASTG, Kh, Vh, (c + 2) * 128, tid);
            asm volatile("cp.async.commit_group;" ::: "memory");
        }
    }

    // ---- epilogue: O/l -> fp16 in (token, 768) layout ----
    const int b = bh / NH;
    const int h = bh - b * NH;
    const float inv0 = 1.f / lacc[0];    // row r sum
    const float inv1 = 1.f / lacc[2];    // row r+8 sum
    const int q = q0 + m0 + (lane >> 2);
    const size_t tok0 = (size_t)(b * SEQ + q) * D_MODEL;
    const size_t tok1 = tok0 + 8 * D_MODEL;
    #pragma unroll
    for (int nj = 0; nj < 8; nj++) {
        const int dc = h * HEADD + nj*8 + (lane & 3)*2;
        *(uint32_t*)&g_oh[tok0 + dc] = pack2h(o[nj][0] * inv0, o[nj][1] * inv0);
        *(uint32_t*)&g_oh[tok1 + dc] = pack2h(o[nj][2] * inv1, o[nj][3] * inv1);
    }
}

// ============================================================
extern "C" void kernel_launch(void* const* d_in, const int* in_sizes, int n_in,
                              void* d_out, int out_size)
{
    const float* x  = (const float*)d_in[0];   // (B,T,768)
    const float* W1 = (const float*)d_in[1];   // (2304,768)
    const float* b1 = (const float*)d_in[2];
    const float* W2 = (const float*)d_in[3];   // (768,768)
    const float* b2 = (const float*)d_in[4];
    float* out = (float*)d_out;

    __half *p_xh, *p_w1h, *p_w2h, *p_oh;
    cudaGetSymbolAddress((void**)&p_xh,  g_xh);
    cudaGetSymbolAddress((void**)&p_w1h, g_w1h);
    cudaGetSymbolAddress((void**)&p_w2h, g_w2h);
    cudaGetSymbolAddress((void**)&p_oh,  g_oh);

    cudaFuncSetAttribute(gemm_mma<0>, cudaFuncAttributeMaxDynamicSharedMemorySize, SMEM_GEMM);
    cudaFuncSetAttribute(gemm_mma<1>, cudaFuncAttributeMaxDynamicSharedMemorySize, SMEM_GEMM);
    cudaFuncSetAttribute(attn_mma,    cudaFuncAttributeMaxDynamicSharedMemorySize, SMEM_ATTN);

    // fused converts (all plain fp16 packs)
    convert_all<<<XBLK + W1BLK + W2BLK, 256>>>(x, W1, W2);

    // 1) QKV projection (fp16 1-pass) -> q (scaled 1/8*log2e), k, v
    gemm_mma<0><<<dim3(N_QKV/128, M_TOK/128), 256, SMEM_GEMM>>>(
        p_xh, p_w1h, b1, nullptr, N_QKV);

    // 2) tensor-core causal flash attention (f16x2 exp + ones-mma l) -> fp16 O
    attn_mma<<<dim3(SEQ/128, BATCH*NH), 256, SMEM_ATTN>>>();

    // 3) output projection (fp16 1-pass)
    gemm_mma<1><<<dim3(D_MODEL/128, M_TOK/128), 256, SMEM_GEMM>>>(
        p_oh, p_w2h, b2, out, D_MODEL);
}